// round 13
// baseline (speedup 1.0000x reference)
#include <cuda_runtime.h>
#include <cuda_fp16.h>

#define NBATCH 1024
#define NHALF 512
#define MDIM 64
#define CDIM 4
#define TSTEPS 100

// One WARP per TWO batch elements (n, n+512). Grid=512, block=32.
// Lane l owns rows l and l+32 of both simulations. The two sims are fully
// independent -> 2x per-warp ILP to cover dependency latency.
// Dot in fp16x2 (HFMA2), p scaled by 1024. No cross-warp barriers.
__global__ __launch_bounds__(32)
void metapop_kernel(const float* __restrict__ R,
                    const float* __restrict__ T,
                    const float* __restrict__ rho0,
                    const float* __restrict__ beta,
                    float* __restrict__ out)
{
    __shared__ float sinv[2][MDIM];
    __shared__ __align__(16) __half2 sp16[2][2][MDIM / 2]; // [sim][buf][word]

    const int n0 = blockIdx.x;       // sim g uses n = n0 + 512*g
    const int l  = threadIdx.x;      // lane 0..31

    // ---- per-sim invariants ----
    __half2 Rpk[2][2][MDIM / 2];     // [g][h][k] = (R[r,k], R[r,k+32]), r=l+32h
    float   Tm[2][CDIM * CDIM];
    float   A_[2][2], B_[2][2];
    float   r0[2][2], r1[2][2], r2[2][2], r3[2][2];
    float   bet[2];

    #pragma unroll
    for (int g = 0; g < 2; g++) {
        const int n = n0 + NHALF * g;
        const float* Rn = R + (size_t)n * MDIM * MDIM;

        // sinv: lane l sums columns l and l+32 (coalesced)
        {
            float sA = 0.0f, sB = 0.0f;
            #pragma unroll 8
            for (int i = 0; i < MDIM; i++) {
                sA += Rn[i * MDIM + l];
                sB += Rn[i * MDIM + l + 32];
            }
            sinv[g][l]      = 1.0f / sA;
            sinv[g][l + 32] = 1.0f / sB;
        }
        __syncwarp();

        // T scalar regs
        const float* Tn = T + (size_t)n * CDIM * CDIM;
        #pragma unroll
        for (int k = 0; k < CDIM * CDIM; k++) Tm[g][k] = Tn[k];

        bet[g] = beta[n];

        #pragma unroll
        for (int h = 0; h < 2; h++) {
            const int r = l + 32 * h;

            #pragma unroll
            for (int k = 0; k < MDIM / 2; k++)
                Rpk[g][h][k] =
                    __floats2half2_rn(Rn[r * MDIM + k], Rn[r * MDIM + k + 32]);

            // x_j = Rt[n,r,j]*sinv[j];
            // Rt[n,r,j] = R[(r&15)*64+j, (n&15)*4+(r>>4), n>>4]
            // p = 1 - prod(1 - c x_j) ~= c*A - c^2*B  (>=c^3 dropped)
            const int b = (n & 15) * 4 + (r >> 4);
            const int a = n >> 4;
            const int cbase = (r & 15) * 64;
            const size_t off = (size_t)b * MDIM + a;
            float s = 0.0f, ss = 0.0f;
            #pragma unroll
            for (int j = 0; j < MDIM; j++) {
                const float x =
                    R[(size_t)(cbase + j) * (MDIM * MDIM) + off] * sinv[g][j];
                s += x;
                ss = fmaf(x, x, ss);
            }
            A_[g][h] = s;
            B_[g][h] = 0.5f * (s * s - ss);

            const float4 rr =
                *(const float4*)(rho0 + ((size_t)n * MDIM + r) * CDIM);
            r0[g][h] = rr.x; r1[g][h] = rr.y; r2[g][h] = rr.z; r3[g][h] = rr.w;
        }
    }

    const float SCALE   = 1024.0f;   // p stored as p*1024 in fp16 (exact pow2)
    const float UNSCALE = 1.0f / 1024.0f;

    float4* outp[2];
    outp[0] = (float4*)out + (size_t)n0 * MDIM + l;
    outp[1] = (float4*)out + (size_t)(n0 + NHALF) * MDIM + l;

    for (int t = 0; t < TSTEPS; t++) {
        const int buf = t & 1;

        // trajectory stores (pre-update) + p production for both sims
        #pragma unroll
        for (int g = 0; g < 2; g++) {
            outp[g][0]  = make_float4(r0[g][0], r1[g][0], r2[g][0], r3[g][0]);
            outp[g][32] = make_float4(r0[g][1], r1[g][1], r2[g][1], r3[g][1]);
            outp[g] += (size_t)NBATCH * MDIM;

            const float c0 = bet[g] * r1[g][0];
            const float c1 = bet[g] * r1[g][1];
            const float p0 = (c0 * fmaf(-c0, B_[g][0], A_[g][0])) * SCALE;
            const float p1 = (c1 * fmaf(-c1, B_[g][1], A_[g][1])) * SCALE;
            sp16[g][buf][l] = __floats2half2_rn(p0, p1);
        }
        __syncwarp();

        // dots: 2 sims x 2 rows, fp16x2; 8 broadcast LDS.128 per sim
        __half2 ac[2][2][4];
        #pragma unroll
        for (int g = 0; g < 2; g++)
            #pragma unroll
            for (int h = 0; h < 2; h++)
                #pragma unroll
                for (int j = 0; j < 4; j++)
                    ac[g][h][j] = __float2half2_rn(0.0f);

        #pragma unroll
        for (int g = 0; g < 2; g++) {
            const uint4* spp = (const uint4*)sp16[g][buf];
            #pragma unroll
            for (int q = 0; q < 8; q++) {       // 8 x 16B = 32 half2 words
                const uint4 v = spp[q];
                const __half2 w0 = *reinterpret_cast<const __half2*>(&v.x);
                const __half2 w1 = *reinterpret_cast<const __half2*>(&v.y);
                const __half2 w2 = *reinterpret_cast<const __half2*>(&v.z);
                const __half2 w3 = *reinterpret_cast<const __half2*>(&v.w);
                #pragma unroll
                for (int h = 0; h < 2; h++) {
                    ac[g][h][0] = __hfma2(Rpk[g][h][4 * q + 0], w0, ac[g][h][0]);
                    ac[g][h][1] = __hfma2(Rpk[g][h][4 * q + 1], w1, ac[g][h][1]);
                    ac[g][h][2] = __hfma2(Rpk[g][h][4 * q + 2], w2, ac[g][h][2]);
                    ac[g][h][3] = __hfma2(Rpk[g][h][4 * q + 3], w3, ac[g][h][3]);
                }
            }
        }
        // (no second syncwarp: double buffer + next step's syncwarp orders
        //  all lanes' reads of buf before any store to buf at t+2)

        #pragma unroll
        for (int g = 0; g < 2; g++) {
            #pragma unroll
            for (int h = 0; h < 2; h++) {
                const __half2 s01 = __hadd2(ac[g][h][0], ac[g][h][1]);
                const __half2 s23 = __hadd2(ac[g][h][2], ac[g][h][3]);
                const float2 f01 = __half22float2(s01);
                const float2 f23 = __half22float2(s23);
                const float dot =
                    ((f01.x + f01.y) + (f23.x + f23.y)) * UNSCALE;

                const float newinf =
                    (1.0f - ((r0[g][h] + r1[g][h]) + (r2[g][h] + r3[g][h]))) * dot;

                // rho_new = rho @ T + newinf*e0, clip below at 0
                float v0 = newinf, v1 = 0.0f, v2 = 0.0f, v3 = 0.0f;
                v0 = fmaf(r0[g][h], Tm[g][0],  v0);
                v1 = fmaf(r0[g][h], Tm[g][1],  v1);
                v2 = fmaf(r0[g][h], Tm[g][2],  v2);
                v3 = fmaf(r0[g][h], Tm[g][3],  v3);
                v0 = fmaf(r1[g][h], Tm[g][4],  v0);
                v1 = fmaf(r1[g][h], Tm[g][5],  v1);
                v2 = fmaf(r1[g][h], Tm[g][6],  v2);
                v3 = fmaf(r1[g][h], Tm[g][7],  v3);
                v0 = fmaf(r2[g][h], Tm[g][8],  v0);
                v1 = fmaf(r2[g][h], Tm[g][9],  v1);
                v2 = fmaf(r2[g][h], Tm[g][10], v2);
                v3 = fmaf(r2[g][h], Tm[g][11], v3);
                v0 = fmaf(r3[g][h], Tm[g][12], v0);
                v1 = fmaf(r3[g][h], Tm[g][13], v1);
                v2 = fmaf(r3[g][h], Tm[g][14], v2);
                v3 = fmaf(r3[g][h], Tm[g][15], v3);
                r0[g][h] = fmaxf(v0, 0.0f);
                r1[g][h] = fmaxf(v1, 0.0f);
                r2[g][h] = fmaxf(v2, 0.0f);
                r3[g][h] = fmaxf(v3, 0.0f);
            }
        }
    }
}

extern "C" void kernel_launch(void* const* d_in, const int* in_sizes, int n_in,
                              void* d_out, int out_size)
{
    const float* R    = (const float*)d_in[0];   // (1024, 64, 64)
    const float* T    = (const float*)d_in[1];   // (1024, 4, 4)
    const float* rho0 = (const float*)d_in[2];   // (1024, 64, 4)
    const float* beta = (const float*)d_in[3];   // (1024,)
    float* out = (float*)d_out;                  // (100, 1024, 64, 4)

    metapop_kernel<<<NHALF, 32>>>(R, T, rho0, beta, out);
}

// round 14
// speedup vs baseline: 1.1199x; 1.1199x over previous
#include <cuda_runtime.h>
#include <cuda_fp16.h>

#define NBATCH 1024
#define MDIM 64
#define CDIM 4
#define TSTEPS 100

// One WARP per batch element n (block=32, grid=1024). Lane l owns rows l and
// l+32. p-exchange via register shuffles (broadcast __shfl_sync): no smem, no
// __syncwarp, no double buffer in the time loop. Dot in fp16x2 (HFMA2), p
// scaled by 1024 to sit in fp16 normal range.
__global__ __launch_bounds__(32)
void metapop_kernel(const float* __restrict__ R,
                    const float* __restrict__ T,
                    const float* __restrict__ rho0,
                    const float* __restrict__ beta,
                    float* __restrict__ out)
{
    __shared__ float sinv[MDIM];     // setup only

    const int n = blockIdx.x;
    const int l = threadIdx.x;       // lane 0..31

    const float* Rn = R + (size_t)n * MDIM * MDIM;

    // ---- sinv: lane l sums columns l and l+32 (coalesced) ----
    {
        float sA = 0.0f, sB = 0.0f;
        #pragma unroll 8
        for (int i = 0; i < MDIM; i++) {
            sA += Rn[i * MDIM + l];
            sB += Rn[i * MDIM + l + 32];
        }
        sinv[l]      = 1.0f / sA;
        sinv[l + 32] = 1.0f / sB;
    }
    __syncwarp();

    // ---- T as 16 scalar registers ----
    float Tm[CDIM * CDIM];
    {
        const float* Tn = T + (size_t)n * CDIM * CDIM;
        #pragma unroll
        for (int k = 0; k < CDIM * CDIM; k++) Tm[k] = Tn[k];
    }

    // ---- per-row invariants ----
    // Rpk[h][k] = half2( R[r,k], R[r,k+32] ), k = 0..31, r = l + 32h.
    // Matches the shuffled word w_k = (p_k, p_{k+32}) elementwise.
    __half2 Rpk[2][MDIM / 2];
    float A_[2], B_[2];
    float r0[2], r1[2], r2[2], r3[2];

    #pragma unroll
    for (int h = 0; h < 2; h++) {
        const int r = l + 32 * h;

        #pragma unroll
        for (int k = 0; k < MDIM / 2; k++)
            Rpk[h][k] = __floats2half2_rn(Rn[r * MDIM + k], Rn[r * MDIM + k + 32]);

        // x_j = Rt[n,r,j]*sinv[j]; Rt[n,r,j] = R[(r&15)*64+j, (n&15)*4+(r>>4), n>>4]
        // p = 1 - prod(1 - c x_j) ~= c*A - c^2*B  (>=c^3 dropped, rel err ~1e-6)
        const int b = (n & 15) * 4 + (r >> 4);
        const int a = n >> 4;
        const int cbase = (r & 15) * 64;
        const size_t off = (size_t)b * MDIM + a;
        float s = 0.0f, ss = 0.0f;
        #pragma unroll
        for (int j = 0; j < MDIM; j++) {
            const float x =
                R[(size_t)(cbase + j) * (MDIM * MDIM) + off] * sinv[j];
            s += x;
            ss = fmaf(x, x, ss);
        }
        A_[h] = s;
        B_[h] = 0.5f * (s * s - ss);

        const float4 rr = *(const float4*)(rho0 + ((size_t)n * MDIM + r) * CDIM);
        r0[h] = rr.x; r1[h] = rr.y; r2[h] = rr.z; r3[h] = rr.w;
    }

    const float bet = beta[n];
    const float SCALE   = 1024.0f;   // p stored as p*1024 in fp16 (exact pow2)
    const float UNSCALE = 1.0f / 1024.0f;

    float4* out4 = (float4*)out + (size_t)n * MDIM + l;

    for (int t = 0; t < TSTEPS; t++) {
        // trajectory = pre-update state (coalesced STG.128 x2)
        out4[0]  = make_float4(r0[0], r1[0], r2[0], r3[0]);
        out4[32] = make_float4(r0[1], r1[1], r2[1], r3[1]);
        out4 += (size_t)NBATCH * MDIM;

        // p_r = c*(A - c*B), scaled; lane k's word = (p_k, p_{k+32})
        const float c0 = bet * r1[0];
        const float c1 = bet * r1[1];
        const float p0 = (c0 * fmaf(-c0, B_[0], A_[0])) * SCALE;
        const float p1 = (c1 * fmaf(-c1, B_[1], A_[1])) * SCALE;
        const __half2 myp = __floats2half2_rn(p0, p1);
        const unsigned mypu = *reinterpret_cast<const unsigned*>(&myp);

        // dot per row: 32 broadcast shuffles + 32 HFMA2/row.
        // w_k = (p_k, p_{k+32}) from lane k; implicit warp sync via shfl.
        __half2 ac[2][4];
        #pragma unroll
        for (int h = 0; h < 2; h++)
            #pragma unroll
            for (int j = 0; j < 4; j++) ac[h][j] = __float2half2_rn(0.0f);

        #pragma unroll
        for (int k = 0; k < MDIM / 2; k++) {
            const unsigned wu = __shfl_sync(0xFFFFFFFFu, mypu, k);
            const __half2 w = *reinterpret_cast<const __half2*>(&wu);
            ac[0][k & 3] = __hfma2(Rpk[0][k], w, ac[0][k & 3]);
            ac[1][k & 3] = __hfma2(Rpk[1][k], w, ac[1][k & 3]);
        }

        #pragma unroll
        for (int h = 0; h < 2; h++) {
            const __half2 s01 = __hadd2(ac[h][0], ac[h][1]);
            const __half2 s23 = __hadd2(ac[h][2], ac[h][3]);
            const float2 f01 = __half22float2(s01);
            const float2 f23 = __half22float2(s23);
            const float dot =
                ((f01.x + f01.y) + (f23.x + f23.y)) * UNSCALE;

            const float newinf =
                (1.0f - ((r0[h] + r1[h]) + (r2[h] + r3[h]))) * dot;

            // rho_new = rho @ T + newinf*e0 (scalar 4x4), clip below at 0
            float v0 = newinf, v1 = 0.0f, v2 = 0.0f, v3 = 0.0f;
            v0 = fmaf(r0[h], Tm[0],  v0);
            v1 = fmaf(r0[h], Tm[1],  v1);
            v2 = fmaf(r0[h], Tm[2],  v2);
            v3 = fmaf(r0[h], Tm[3],  v3);
            v0 = fmaf(r1[h], Tm[4],  v0);
            v1 = fmaf(r1[h], Tm[5],  v1);
            v2 = fmaf(r1[h], Tm[6],  v2);
            v3 = fmaf(r1[h], Tm[7],  v3);
            v0 = fmaf(r2[h], Tm[8],  v0);
            v1 = fmaf(r2[h], Tm[9],  v1);
            v2 = fmaf(r2[h], Tm[10], v2);
            v3 = fmaf(r2[h], Tm[11], v3);
            v0 = fmaf(r3[h], Tm[12], v0);
            v1 = fmaf(r3[h], Tm[13], v1);
            v2 = fmaf(r3[h], Tm[14], v2);
            v3 = fmaf(r3[h], Tm[15], v3);
            r0[h] = fmaxf(v0, 0.0f);
            r1[h] = fmaxf(v1, 0.0f);
            r2[h] = fmaxf(v2, 0.0f);
            r3[h] = fmaxf(v3, 0.0f);
        }
    }
}

extern "C" void kernel_launch(void* const* d_in, const int* in_sizes, int n_in,
                              void* d_out, int out_size)
{
    const float* R    = (const float*)d_in[0];   // (1024, 64, 64)
    const float* T    = (const float*)d_in[1];   // (1024, 4, 4)
    const float* rho0 = (const float*)d_in[2];   // (1024, 64, 4)
    const float* beta = (const float*)d_in[3];   // (1024,)
    float* out = (float*)d_out;                  // (100, 1024, 64, 4)

    metapop_kernel<<<NBATCH, 32>>>(R, T, rho0, beta, out);
}